// round 15
// baseline (speedup 1.0000x reference)
#include <cuda_runtime.h>

// QConv1D quantum sim, FINAL (R9 config; best measured 6.656us total, twice;
// identical-binary noise band 6.66-6.91us established over 4 runs).
//
// Algorithm: closed form via Heisenberg conjugation. Measurement Z^(x8) pulled
// back through the final CZ layer (diagonal -> drops), the layer-1 RYs
// (Z -> cos(p1) Z - sin(p1) X), and the CZ chain (X_q -> X_q Z_{q-1} Z_{q+1});
// evaluated on the product state produced by the fused RY(x_q)+RY(p0_q) layer
// (RY angles add). Surviving Pauli terms correspond exactly to independent
// sets of the 8-qubit chain, giving a 3-state transfer-matrix DP:
//   per qubit: C=cos(x+p0), S=sin(x+p0), u=-sin(p1)S, scale cos(p1) on Z-legs.
// One THREAD per (position, out-channel) sim; ~80 FLOPs per output.
//
// Mapping: 8 consecutive lanes = one conv position x 8 out-channels (u=lane&7).
//  - x trig: one __sincosf per lane (lane's u doubles as its trig qubit),
//    exchanged via intra-group shfl.
//  - weight trig: lane computes (o=u, q=g) and (o=u, q=g+4), g=lane>>3, both
//    layers (4 __sincosf), distributed by per-lane-src shfl.
// No smem, no barriers; 128 CTAs x 512 threads = single wave on 148 SMs.
// Output address replicates the reference's reshape reinterpretation of the
// flat [o][n] result buffer as [b'][p'][o'].
constexpr int O_CH  = 8;
constexpr int NQ    = 8;
constexpr int L_IN  = 512;
constexpr int L_OUT = 509;
constexpr int B_SZ  = 16;
constexpr int N_POS = B_SZ * L_OUT;          // 8144 (multiple of 8)
constexpr int TPB   = 512;
constexpr int POS_PER_BLK = TPB / O_CH;      // 64

__global__ __launch_bounds__(TPB)
void qconv_kernel(const float* __restrict__ x,
                  const float* __restrict__ w,
                  float* __restrict__ out)
{
    const int tid  = threadIdx.x;
    const int lane = tid & 31;
    const int u    = lane & 7;               // o-channel AND x-trig qubit
    const int g    = lane >> 3;              // 0..3: weight-trig q slot

    // --- this thread's sim position (x load issued FIRST)
    const int n_raw = blockIdx.x * POS_PER_BLK + (tid >> 3);
    const bool valid = (n_raw < N_POS);
    const int n   = valid ? n_raw : N_POS - 1;
    const int bb  = n / L_OUT;
    const int pos = n - bb * L_OUT;
    const float xv = x[(bb * 2 + (u >> 2)) * L_IN + pos + (u & 3)];

    // --- weight loads for (o=u, q=g) and (o=u, q=g+4); w layout (O, NQ, 2)
    const float2 wa = reinterpret_cast<const float2*>(w)[u * NQ + g];      // {p0, p1} @ q=g
    const float2 wb = reinterpret_cast<const float2*>(w)[u * NQ + g + 4];  // {p0, p1} @ q=g+4

    float c0a, s0a, c1a, s1a, c0b, s0b, c1b, s1b, cx, sx;
    __sincosf(wa.x, &s0a, &c0a);
    __sincosf(wa.y, &s1a, &c1a);
    __sincosf(wb.x, &s0b, &c0b);
    __sincosf(wb.y, &s1b, &c1b);
    __sincosf(xv,   &sx,  &cx);

    // --- output indexing (overlaps trig latency)
    //     flat sim s = u*8144 + n ; oo = n&7 ; bo = 2u + (n>>3 >= 509)
    const int oo = n & 7;
    const int nh = n >> 3;                   // 0..1017
    const int hi = (nh >= L_OUT) ? 1 : 0;
    const int po = nh - hi * L_OUT;
    float* const optr = out + ((2 * u + hi) * O_CH + oo) * L_OUT + po;

    const int gbase = lane & 24;             // 8-lane group base within warp

    // --- 3-state transfer-matrix DP over the 8-qubit chain.
    // Coefficient (u, q) lives at lane u + 8*(q&3), set a for q<4 else b.
    float v00 = 1.f, v01 = 1.f, v10 = 0.f;
#pragma unroll
    for (int q = 0; q < NQ; q++) {
        const int wsrc = u + ((q & 3) << 3);
        const float c0 = __shfl_sync(0xffffffffu, (q < 4) ? c0a : c0b, wsrc);
        const float s0 = __shfl_sync(0xffffffffu, (q < 4) ? s0a : s0b, wsrc);
        const float c1 = __shfl_sync(0xffffffffu, (q < 4) ? c1a : c1b, wsrc);
        const float s1 = __shfl_sync(0xffffffffu, (q < 4) ? s1a : s1b, wsrc);
        const float cxq = __shfl_sync(0xffffffffu, cx, gbase + q);
        const float sxq = __shfl_sync(0xffffffffu, sx, gbase + q);
        const float C  = cxq * c0 - sxq * s0;       // cos(x+p0)
        const float S  = sxq * c0 + cxq * s0;       // sin(x+p0)
        const float uu  = -s1 * S;                  // -sin(p1) sin(x+p0)
        const float n00 = c1 * fmaf(v00, C, v10);
        const float n01 = c1 * fmaf(v10, C, v00);
        const float n10 = uu * v01;
        v00 = n00; v01 = n01; v10 = n10;
    }

    if (valid) *optr = v00 + v10;                   // boundary b_8 = 0
}

extern "C" void kernel_launch(void* const* d_in, const int* in_sizes, int n_in,
                              void* d_out, int out_size)
{
    const float* x = (const float*)d_in[0];
    const float* w = (const float*)d_in[1];
    float* out = (float*)d_out;
    const int blocks = (N_POS + POS_PER_BLK - 1) / POS_PER_BLK;   // 128
    qconv_kernel<<<blocks, TPB>>>(x, w, out);
}

// round 16
// speedup vs baseline: 1.0337x; 1.0337x over previous
#include <cuda_runtime.h>

// QConv1D quantum sim, FINAL (R9 config; best measured 6.656us total, twice;
// identical-binary noise band 6.66-6.91us established over 5 runs).
//
// Algorithm: closed form via Heisenberg conjugation. Measurement Z^(x8) pulled
// back through the final CZ layer (diagonal -> drops), the layer-1 RYs
// (Z -> cos(p1) Z - sin(p1) X), and the CZ chain (X_q -> X_q Z_{q-1} Z_{q+1});
// evaluated on the product state produced by the fused RY(x_q)+RY(p0_q) layer
// (RY angles add). Surviving Pauli terms correspond exactly to independent
// sets of the 8-qubit chain, giving a 3-state transfer-matrix DP:
//   per qubit: C=cos(x+p0), S=sin(x+p0), u=-sin(p1)S, scale cos(p1) on Z-legs.
// One THREAD per (position, out-channel) sim; ~80 FLOPs per output.
//
// Mapping: 8 consecutive lanes = one conv position x 8 out-channels (u=lane&7).
//  - x trig: one __sincosf per lane (lane's u doubles as its trig qubit),
//    exchanged via intra-group shfl.
//  - weight trig: lane computes (o=u, q=g) and (o=u, q=g+4), g=lane>>3, both
//    layers (4 __sincosf), distributed by per-lane-src shfl.
// No smem, no barriers; 128 CTAs x 512 threads = single wave on 148 SMs.
// Output address replicates the reference's reshape reinterpretation of the
// flat [o][n] result buffer as [b'][p'][o'].
constexpr int O_CH  = 8;
constexpr int NQ    = 8;
constexpr int L_IN  = 512;
constexpr int L_OUT = 509;
constexpr int B_SZ  = 16;
constexpr int N_POS = B_SZ * L_OUT;          // 8144 (multiple of 8)
constexpr int TPB   = 512;
constexpr int POS_PER_BLK = TPB / O_CH;      // 64

__global__ __launch_bounds__(TPB)
void qconv_kernel(const float* __restrict__ x,
                  const float* __restrict__ w,
                  float* __restrict__ out)
{
    const int tid  = threadIdx.x;
    const int lane = tid & 31;
    const int u    = lane & 7;               // o-channel AND x-trig qubit
    const int g    = lane >> 3;              // 0..3: weight-trig q slot

    // --- this thread's sim position (x load issued FIRST)
    const int n_raw = blockIdx.x * POS_PER_BLK + (tid >> 3);
    const bool valid = (n_raw < N_POS);
    const int n   = valid ? n_raw : N_POS - 1;
    const int bb  = n / L_OUT;
    const int pos = n - bb * L_OUT;
    const float xv = x[(bb * 2 + (u >> 2)) * L_IN + pos + (u & 3)];

    // --- weight loads for (o=u, q=g) and (o=u, q=g+4); w layout (O, NQ, 2)
    const float2 wa = reinterpret_cast<const float2*>(w)[u * NQ + g];      // {p0, p1} @ q=g
    const float2 wb = reinterpret_cast<const float2*>(w)[u * NQ + g + 4];  // {p0, p1} @ q=g+4

    float c0a, s0a, c1a, s1a, c0b, s0b, c1b, s1b, cx, sx;
    __sincosf(wa.x, &s0a, &c0a);
    __sincosf(wa.y, &s1a, &c1a);
    __sincosf(wb.x, &s0b, &c0b);
    __sincosf(wb.y, &s1b, &c1b);
    __sincosf(xv,   &sx,  &cx);

    // --- output indexing (overlaps trig latency)
    //     flat sim s = u*8144 + n ; oo = n&7 ; bo = 2u + (n>>3 >= 509)
    const int oo = n & 7;
    const int nh = n >> 3;                   // 0..1017
    const int hi = (nh >= L_OUT) ? 1 : 0;
    const int po = nh - hi * L_OUT;
    float* const optr = out + ((2 * u + hi) * O_CH + oo) * L_OUT + po;

    const int gbase = lane & 24;             // 8-lane group base within warp

    // --- 3-state transfer-matrix DP over the 8-qubit chain.
    // Coefficient (u, q) lives at lane u + 8*(q&3), set a for q<4 else b.
    float v00 = 1.f, v01 = 1.f, v10 = 0.f;
#pragma unroll
    for (int q = 0; q < NQ; q++) {
        const int wsrc = u + ((q & 3) << 3);
        const float c0 = __shfl_sync(0xffffffffu, (q < 4) ? c0a : c0b, wsrc);
        const float s0 = __shfl_sync(0xffffffffu, (q < 4) ? s0a : s0b, wsrc);
        const float c1 = __shfl_sync(0xffffffffu, (q < 4) ? c1a : c1b, wsrc);
        const float s1 = __shfl_sync(0xffffffffu, (q < 4) ? s1a : s1b, wsrc);
        const float cxq = __shfl_sync(0xffffffffu, cx, gbase + q);
        const float sxq = __shfl_sync(0xffffffffu, sx, gbase + q);
        const float C  = cxq * c0 - sxq * s0;       // cos(x+p0)
        const float S  = sxq * c0 + cxq * s0;       // sin(x+p0)
        const float uu  = -s1 * S;                  // -sin(p1) sin(x+p0)
        const float n00 = c1 * fmaf(v00, C, v10);
        const float n01 = c1 * fmaf(v10, C, v00);
        const float n10 = uu * v01;
        v00 = n00; v01 = n01; v10 = n10;
    }

    if (valid) *optr = v00 + v10;                   // boundary b_8 = 0
}

extern "C" void kernel_launch(void* const* d_in, const int* in_sizes, int n_in,
                              void* d_out, int out_size)
{
    const float* x = (const float*)d_in[0];
    const float* w = (const float*)d_in[1];
    float* out = (float*)d_out;
    const int blocks = (N_POS + POS_PER_BLK - 1) / POS_PER_BLK;   // 128
    qconv_kernel<<<blocks, TPB>>>(x, w, out);
}